// round 1
// baseline (speedup 1.0000x reference)
#include <cuda_runtime.h>

// pyGAMNet: B x 64 inputs. Cols 0..47: per-feature scalar MLP 1->40->20->1 (ReLU).
// Cols 48..63: class_bias[c, (int)x] gather.
//
// Inputs (metadata order):
//  d_in[0] inputs  [131072*64] f32
//  d_in[1] W0      [48*1*40]   f32
//  d_in[2] b0      [48*40]     f32
//  d_in[3] W1      [48*40*20]  f32
//  d_in[4] b1      [48*20]     f32
//  d_in[5] W2      [48*20*1]   f32
//  d_in[6] b2      [48*1]      f32
//  d_in[7] class_bias [16*32]  f32
// Output: [131072*64] f32

#define BSZ   131072
#define NCOL  64
#define NF    48
#define H0N   40
#define H1N   20
#define TPB   256
#define RPT   2
#define ROWS_BLK (TPB * RPT)   // 512 rows per block

typedef unsigned long long u64;

__device__ __forceinline__ u64 pk2(float lo, float hi) {
    u64 r;
    asm("mov.b64 %0, {%1,%2};" : "=l"(r) : "f"(lo), "f"(hi));
    return r;
}
__device__ __forceinline__ float2 up2(u64 v) {
    float2 o;
    asm("mov.b64 {%0,%1}, %2;" : "=f"(o.x), "=f"(o.y) : "l"(v));
    return o;
}
// Packed dual-FMA: d.lo = a.lo*b.lo + c.lo ; d.hi = a.hi*b.hi + c.hi
__device__ __forceinline__ u64 ffma2(u64 a, u64 b, u64 c) {
    u64 d;
    asm("fma.rn.f32x2 %0, %1, %2, %3;" : "=l"(d) : "l"(a), "l"(b), "l"(c));
    return d;
}
__device__ __forceinline__ u64 relu2(u64 v) {
    float2 f = up2(v);
    return pk2(fmaxf(f.x, 0.f), fmaxf(f.y, 0.f));
}

// One block = one numeric feature x 512 rows. Thread handles 2 rows.
// Layer-1 neurons paired (k,k+1) into f32x2 lanes: W1 row pairs are contiguous
// so they load as one 8B shared load; h0 is broadcast-packed once per j.
__global__ __launch_bounds__(TPB) void gam_num_kernel(
    const float* __restrict__ in,
    const float* __restrict__ W0, const float* __restrict__ b0,
    const float* __restrict__ W1, const float* __restrict__ b1,
    const float* __restrict__ W2, const float* __restrict__ b2,
    float* __restrict__ out)
{
    __shared__ __align__(8) float sW1[H0N * H1N];  // [j][k], k-contiguous
    __shared__ __align__(8) float sW0[H0N];
    __shared__ __align__(8) float sB0[H0N];
    __shared__ __align__(8) float sB1[H1N];
    __shared__ __align__(8) float sW2[H1N];
    __shared__ float sB2;

    const int n   = blockIdx.y;      // feature 0..47
    const int tid = threadIdx.x;

    for (int i = tid; i < H0N * H1N; i += TPB) sW1[i] = W1[n * H0N * H1N + i];
    if (tid < H0N) {
        sW0[tid] = W0[n * H0N + tid];
        sB0[tid] = b0[n * H0N + tid];
    } else if (tid < H0N + H1N) {
        int k = tid - H0N;
        sB1[k] = b1[n * H1N + k];
        sW2[k] = W2[n * H1N + k];
    } else if (tid == H0N + H1N) {
        sB2 = b2[n];
    }
    __syncthreads();

    const int r0 = blockIdx.x * ROWS_BLK + tid;  // <= 131071, fits int math
    const int r1 = r0 + TPB;

    const float x0 = in[r0 * NCOL + n];
    const float x1 = in[r1 * NCOL + n];

    // h1 accumulators: 10 f32x2 pairs per row, init with b1
    u64 acc0[H1N / 2], acc1[H1N / 2];
    #pragma unroll
    for (int kk = 0; kk < H1N / 2; kk++) {
        u64 p = reinterpret_cast<const u64*>(sB1)[kk];
        acc0[kk] = p;
        acc1[kk] = p;
    }

    #pragma unroll 4
    for (int j = 0; j < H0N; j++) {
        const float w0j = sW0[j];
        const float b0j = sB0[j];
        const float h0a = fmaxf(fmaf(x0, w0j, b0j), 0.f);
        const float h0b = fmaxf(fmaf(x1, w0j, b0j), 0.f);
        const u64 h0ap = pk2(h0a, h0a);
        const u64 h0bp = pk2(h0b, h0b);
        const u64* wrow = reinterpret_cast<const u64*>(sW1 + j * H1N);
        #pragma unroll
        for (int kk = 0; kk < H1N / 2; kk++) {
            const u64 wp = wrow[kk];       // single LDS.64, broadcast
            acc0[kk] = ffma2(h0ap, wp, acc0[kk]);
            acc1[kk] = ffma2(h0bp, wp, acc1[kk]);
        }
    }

    // Layer 2: out = b2 + sum_k relu(h1_k) * W2_k
    u64 o0 = pk2(sB2, 0.f);
    u64 o1 = o0;
    #pragma unroll
    for (int kk = 0; kk < H1N / 2; kk++) {
        const u64 wp = reinterpret_cast<const u64*>(sW2)[kk];
        o0 = ffma2(relu2(acc0[kk]), wp, o0);
        o1 = ffma2(relu2(acc1[kk]), wp, o1);
    }
    const float2 f0 = up2(o0);
    const float2 f1 = up2(o1);
    out[r0 * NCOL + n] = f0.x + f0.y;
    out[r1 * NCOL + n] = f1.x + f1.y;
}

// Categorical columns: out[:, 48+c] = class_bias[c, (int)in[:, 48+c]]
__global__ __launch_bounds__(TPB) void gam_cat_kernel(
    const float* __restrict__ in,
    const float* __restrict__ cb,
    float* __restrict__ out)
{
    __shared__ float scb[16 * 32];
    const int tid = threadIdx.x;
    for (int i = tid; i < 16 * 32; i += TPB) scb[i] = cb[i];
    __syncthreads();

    const int r = blockIdx.x * TPB + tid;
    const float4* src = reinterpret_cast<const float4*>(in + r * NCOL + 48);
    float4* dst = reinterpret_cast<float4*>(out + r * NCOL + 48);

    #pragma unroll
    for (int q = 0; q < 4; q++) {
        float4 v = src[q];
        float4 o;
        o.x = scb[(q * 4 + 0) * 32 + (int)v.x];
        o.y = scb[(q * 4 + 1) * 32 + (int)v.y];
        o.z = scb[(q * 4 + 2) * 32 + (int)v.z];
        o.w = scb[(q * 4 + 3) * 32 + (int)v.w];
        dst[q] = o;
    }
}

extern "C" void kernel_launch(void* const* d_in, const int* in_sizes, int n_in,
                              void* d_out, int out_size)
{
    const float* in = (const float*)d_in[0];
    const float* W0 = (const float*)d_in[1];
    const float* b0 = (const float*)d_in[2];
    const float* W1 = (const float*)d_in[3];
    const float* b1 = (const float*)d_in[4];
    const float* W2 = (const float*)d_in[5];
    const float* b2 = (const float*)d_in[6];
    const float* cb = (const float*)d_in[7];
    float* out = (float*)d_out;

    dim3 gnum(BSZ / ROWS_BLK, NF, 1);   // 256 x 48 blocks
    gam_num_kernel<<<gnum, TPB>>>(in, W0, b0, W1, b1, W2, b2, out);

    gam_cat_kernel<<<BSZ / TPB, TPB>>>(in, cb, out);
}

// round 2
// speedup vs baseline: 1.8686x; 1.8686x over previous
#include <cuda_runtime.h>
#include <math.h>

// pyGAMNet: B x 64 inputs. Cols 0..47: per-feature scalar MLP 1->40->20->1 (ReLU).
// Cols 48..63: class_bias[c, (int)x] gather.
//
// Strategy: each feature's layer0+layer1 pre-activation is piecewise-LINEAR in x
// with breakpoints at t_j = -b0_j/w0_j. Precompute, per feature, per interval
// (41 intervals from 40 sorted thresholds), the collapsed (a_k, c_k) for each of
// the 20 hidden-2 neurons. Eval = binary search for interval + 20x(fma,max,fma).

#define BSZ   131072
#define NCOL  64
#define NF    48
#define H0N   40
#define H1N   20
#define NSEG  41

#define TPB   256
#define RPT   8
#define ROWS_BLK (TPB * RPT)   // 2048 rows per eval block

__device__ float  g_thr[NF][64];            // sorted thresholds, padded with +INF
__device__ float2 g_ac[NF][H1N * NSEG];     // [feature][k*41 + seg] -> (a, c)

#define F_INF  __int_as_float(0x7f800000)
#define F_NINF __int_as_float(0xff800000)

// ---------------------------------------------------------------------------
// Precompute: one block per feature. Builds sorted thresholds + interval table.
// ---------------------------------------------------------------------------
__global__ void gam_precompute_kernel(
    const float* __restrict__ W0, const float* __restrict__ b0,
    const float* __restrict__ W1, const float* __restrict__ b1)
{
    __shared__ float sw0[H0N], sb0[H0N], sthr[H0N];
    __shared__ float ssthr[H0N];
    __shared__ int   ssidx[H0N];

    const int n = blockIdx.x;
    const int t = threadIdx.x;

    if (t < H0N) {
        float w = W0[n * H0N + t];
        float b = b0[n * H0N + t];
        sw0[t] = w;
        sb0[t] = b;
        float thr;
        if (w != 0.0f) thr = -b / w;
        else           thr = (b > 0.0f) ? F_NINF : F_INF;  // always / never active
        sthr[t] = thr;
    }
    __syncthreads();

    // rank sort (stable) of 40 thresholds
    if (t < H0N) {
        float v = sthr[t];
        int r = 0;
        for (int m = 0; m < H0N; m++) {
            float u = sthr[m];
            r += (u < v) || (u == v && m < t);
        }
        ssthr[r] = v;
        ssidx[r] = t;
    }
    __syncthreads();

    if (t < 64) g_thr[n][t] = (t < H0N) ? ssthr[t] : F_INF;

    // Sweep: one thread per hidden-2 neuron k.
    // Interval i = { x : ssthr[i-1] < x < ssthr[i] }; seg index = #(thr < x) = i.
    // Active set at x -> -inf: { j : w0_j < 0 }. Crossing thr toggles:
    //   w0_j > 0 (or ==0 special) -> ON;  w0_j < 0 -> OFF.
    if (t < H1N) {
        float a = 0.0f;
        float c = b1[n * H1N + t];
        for (int j = 0; j < H0N; j++) {
            if (sw0[j] < 0.0f) {
                float w1 = W1[n * H0N * H1N + j * H1N + t];
                a += w1 * sw0[j];
                c += w1 * sb0[j];
            }
        }
        for (int i = 0; i < NSEG; i++) {
            g_ac[n][t * NSEG + i] = make_float2(a, c);
            if (i < H0N) {
                int j = ssidx[i];
                float w1 = W1[n * H0N * H1N + j * H1N + t];
                float da = w1 * sw0[j];
                float dc = w1 * sb0[j];
                if (sw0[j] < 0.0f) { a -= da; c -= dc; }
                else               { a += da; c += dc; }
            }
        }
    }
}

// ---------------------------------------------------------------------------
// Eval: block = (2048 rows) x (1 feature). Binary search + 20-neuron collapse.
// ---------------------------------------------------------------------------
__global__ __launch_bounds__(TPB) void gam_eval_kernel(
    const float* __restrict__ in,
    const float* __restrict__ W2, const float* __restrict__ b2,
    float* __restrict__ out)
{
    __shared__ float  sT[64];
    __shared__ float2 sAC[H1N * NSEG];

    const int n   = blockIdx.y;
    const int tid = threadIdx.x;

    if (tid < 64) sT[tid] = g_thr[n][tid];
    for (int i = tid; i < H1N * NSEG; i += TPB) sAC[i] = g_ac[n][i];

    float w2r[H1N];
    #pragma unroll
    for (int k = 0; k < H1N; k++) w2r[k] = __ldg(&W2[n * H1N + k]);
    const float b2n = __ldg(&b2[n]);
    __syncthreads();

    const int base = blockIdx.x * ROWS_BLK + tid;

    #pragma unroll
    for (int e = 0; e < RPT; e++) {
        const int row = base + e * TPB;
        const float x = __ldg(&in[row * NCOL + n]);

        // branchless binary count: p = #{ sorted thr < x }, p in [0, 40]
        int p = 0;
        if (sT[p + 31] < x) p += 32;
        if (sT[p + 15] < x) p += 16;
        if (sT[p +  7] < x) p +=  8;
        if (sT[p +  3] < x) p +=  4;
        if (sT[p +  1] < x) p +=  2;
        if (sT[p     ] < x) p +=  1;

        float acc = b2n;
        #pragma unroll
        for (int k = 0; k < H1N; k++) {
            const float2 ac = sAC[k * NSEG + p];
            const float h = fmaxf(fmaf(ac.x, x, ac.y), 0.0f);
            acc = fmaf(w2r[k], h, acc);
        }
        out[row * NCOL + n] = acc;
    }
}

// ---------------------------------------------------------------------------
// Categorical columns: out[:, 48+c] = class_bias[c, (int)in[:, 48+c]]
// One thread per float4 quad (4x parallelism vs row-per-thread).
// ---------------------------------------------------------------------------
__global__ __launch_bounds__(TPB) void gam_cat_kernel(
    const float* __restrict__ in,
    const float* __restrict__ cb,
    float* __restrict__ out)
{
    __shared__ float scb[16 * 32];
    const int tid = threadIdx.x;
    for (int i = tid; i < 16 * 32; i += TPB) scb[i] = cb[i];
    __syncthreads();

    const int idx = blockIdx.x * TPB + tid;   // 0 .. B*4-1
    const int row = idx >> 2;
    const int q   = idx & 3;

    const float4 v = reinterpret_cast<const float4*>(in + row * NCOL + 48)[q];
    float4 o;
    o.x = scb[(q * 4 + 0) * 32 + (int)v.x];
    o.y = scb[(q * 4 + 1) * 32 + (int)v.y];
    o.z = scb[(q * 4 + 2) * 32 + (int)v.z];
    o.w = scb[(q * 4 + 3) * 32 + (int)v.w];
    reinterpret_cast<float4*>(out + row * NCOL + 48)[q] = o;
}

extern "C" void kernel_launch(void* const* d_in, const int* in_sizes, int n_in,
                              void* d_out, int out_size)
{
    const float* in = (const float*)d_in[0];
    const float* W0 = (const float*)d_in[1];
    const float* b0 = (const float*)d_in[2];
    const float* W1 = (const float*)d_in[3];
    const float* b1 = (const float*)d_in[4];
    const float* W2 = (const float*)d_in[5];
    const float* b2 = (const float*)d_in[6];
    const float* cb = (const float*)d_in[7];
    float* out = (float*)d_out;

    gam_precompute_kernel<<<NF, 64>>>(W0, b0, W1, b1);

    dim3 gnum(BSZ / ROWS_BLK, NF, 1);   // 64 x 48 blocks
    gam_eval_kernel<<<gnum, TPB>>>(in, W2, b2, out);

    gam_cat_kernel<<<(BSZ * 4) / TPB, TPB>>>(in, cb, out);
}

// round 3
// speedup vs baseline: 3.7300x; 1.9961x over previous
#include <cuda_runtime.h>
#include <math.h>

// pyGAMNet on GB300. Cols 0..47: per-feature scalar MLP 1->40->20->1 (ReLU).
// Cols 48..63: class_bias[c, (int)x] gather.
//
// Full collapse: each feature's MLP is a single piecewise-linear function of x.
//   breakpoints = 40 thresholds t_j=-b0_j/w0_j  +  zero crossings of the 20
//   collapsed hidden-2 pre-activations inside each interval (<= 861 segments).
// Eval = 10-step binary search in smem + one fma.

#define BSZ   131072
#define NCOL  64
#define NF    48
#define H0N   40
#define H1N   20
#define PADN  1024            // padded table size (max segments 861)

#define TPB   256
#define RPT   8
#define ROWS_BLK (TPB * RPT)  // 2048 rows per eval block

#define F_INF  __int_as_float(0x7f800000)

__device__ float  g_bp[NF][PADN];   // sorted breakpoints, +INF padded
__device__ float2 g_AC[NF][PADN];   // per-segment (A, C): f = A*x + C

// ---------------------------------------------------------------------------
// Precompute: one block (256 thr) per feature.
// ---------------------------------------------------------------------------
__global__ __launch_bounds__(256) void gam_precompute_kernel(
    const float* __restrict__ W0, const float* __restrict__ b0,
    const float* __restrict__ W1, const float* __restrict__ b1,
    const float* __restrict__ W2, const float* __restrict__ b2)
{
    __shared__ float sw0[H0N], sb0[H0N], sthr[H0N];
    __shared__ float ssthr[H0N];
    __shared__ int   ssidx[H0N];
    __shared__ float sW1[H0N * H1N];     // [j][k]
    __shared__ float sb1[H1N], sw2[H1N];
    __shared__ float sb2;
    __shared__ float sak[41][H1N], sck[41][H1N];   // per-interval collapsed lines
    __shared__ float crossZ[41][H1N];
    __shared__ int   crossK[41][H1N];
    __shared__ int   cnt[41], offs[42];

    const int n = blockIdx.x;
    const int t = threadIdx.x;

    for (int i = t; i < H0N * H1N; i += 256) sW1[i] = W1[n * H0N * H1N + i];
    if (t < H0N) {
        float w = W0[n * H0N + t];
        float b = b0[n * H0N + t];
        sw0[t] = w; sb0[t] = b;
        sthr[t] = (w != 0.0f) ? (-b / w) : ((b > 0.0f) ? -F_INF : F_INF);
    }
    if (t >= 64 && t < 64 + H1N) sb1[t - 64] = b1[n * H1N + (t - 64)];
    if (t >= 96 && t < 96 + H1N) sw2[t - 96] = W2[n * H1N + (t - 96)];
    if (t == 128) sb2 = b2[n];
    __syncthreads();

    // stable rank-sort of 40 thresholds
    if (t < H0N) {
        float v = sthr[t];
        int r = 0;
        for (int m = 0; m < H0N; m++) {
            float u = sthr[m];
            r += (u < v) || (u == v && m < t);
        }
        ssthr[r] = v;
        ssidx[r] = t;
    }
    __syncthreads();

    // per-(interval i, neuron k): collapsed line a*x + c over interval i
    // interval i = { x : #(thr < x) == i }
    for (int idx = t; idx < 41 * H1N; idx += 256) {
        const int i = idx / H1N;
        const int k = idx % H1N;
        float a = 0.0f, c = sb1[k];
        for (int r = 0; r < H0N; r++) {
            const int j = ssidx[r];
            const float w0 = sw0[j];
            const bool act = (w0 < 0.0f) ? (r >= i) : (r < i);
            if (act) {
                const float w1v = sW1[j * H1N + k];
                a = fmaf(w1v, w0, a);
                c = fmaf(w1v, sb0[j], c);
            }
        }
        sak[i][k] = a;
        sck[i][k] = c;
    }
    __syncthreads();

    // per interval: find interior zero crossings of each neuron line (sorted)
    if (t < 41) {
        const int i = t;
        const float lo = (i == 0)  ? -F_INF : ssthr[i - 1];
        const float hi = (i == 40) ?  F_INF : ssthr[i];
        int c = 0;
        for (int k = 0; k < H1N; k++) {
            const float a = sak[i][k];
            if (a != 0.0f) {
                const float z = -sck[i][k] / a;
                if (z > lo && z < hi) {
                    int p = c++;
                    while (p > 0 && crossZ[i][p - 1] > z) {
                        crossZ[i][p] = crossZ[i][p - 1];
                        crossK[i][p] = crossK[i][p - 1];
                        p--;
                    }
                    crossZ[i][p] = z;
                    crossK[i][p] = k;
                }
            }
        }
        cnt[i] = c;
    }
    __syncthreads();

    if (t == 0) {
        int s = 0;
        for (int i = 0; i < 41; i++) { offs[i] = s; s += cnt[i] + 1; }
        offs[41] = s;
    }
    __syncthreads();
    const int total = offs[41];   // total segments (<= 861)

    // emit segments: sweep activity inside each interval
    if (t < 41) {
        const int i = t;
        const float lo = (i == 0) ? -F_INF : ssthr[i - 1];
        unsigned actm = 0;
        float A = 0.0f, C = sb2;
        for (int k = 0; k < H1N; k++) {
            const float a = sak[i][k], cc = sck[i][k];
            bool av;
            if (a == 0.0f)      av = (cc > 0.0f);
            else if (i == 0)    av = (a < 0.0f);
            else {
                const float v = fmaf(a, lo, cc);
                av = (v > 0.0f) || (v == 0.0f && a > 0.0f);
            }
            if (av) {
                actm |= (1u << k);
                A = fmaf(sw2[k], a,  A);
                C = fmaf(sw2[k], cc, C);
            }
        }
        const int base = offs[i];
        g_AC[n][base] = make_float2(A, C);
        for (int s = 0; s < cnt[i]; s++) {
            g_bp[n][base + s] = crossZ[i][s];
            const int k = crossK[i][s];
            const float sgn = (actm >> k) & 1u ? -1.0f : 1.0f;
            actm ^= (1u << k);
            A = fmaf(sgn * sw2[k], sak[i][k], A);
            C = fmaf(sgn * sw2[k], sck[i][k], C);
            g_AC[n][base + s + 1] = make_float2(A, C);
        }
        if (i < 40) g_bp[n][base + cnt[i]] = ssthr[i];
    }

    // pad breakpoints with +INF (valid bp indices are 0..total-2)
    for (int j = total - 1 + t; j < PADN; j += 256) g_bp[n][j] = F_INF;
}

// ---------------------------------------------------------------------------
// Eval (fused num + cat). Block = 2048 rows x 4 columns.
//  grid.y 0..11  : numeric groups (cols 4g..4g+3), PWL search + 1 fma
//  grid.y 12..15 : categorical groups (cols 48..63), table gather
// ---------------------------------------------------------------------------
__global__ __launch_bounds__(TPB) void gam_eval_kernel(
    const float* __restrict__ in,
    const float* __restrict__ cb,
    float* __restrict__ out)
{
    const int g   = blockIdx.y;
    const int tid = threadIdx.x;
    const int rbase = blockIdx.x * ROWS_BLK + tid;

    if (g < 12) {
        __shared__ float  sB[4][PADN];
        __shared__ float2 sAC[4][PADN];
        #pragma unroll
        for (int f = 0; f < 4; f++) {
            const int n = g * 4 + f;
            for (int i = tid; i < PADN; i += TPB) {
                sB[f][i]  = g_bp[n][i];
                sAC[f][i] = g_AC[n][i];
            }
        }
        __syncthreads();

        #pragma unroll
        for (int e = 0; e < RPT; e++) {
            const int row = rbase + e * TPB;
            const float4 v = *reinterpret_cast<const float4*>(in + row * NCOL + g * 4);
            const float xs[4] = {v.x, v.y, v.z, v.w};
            float os[4];
            #pragma unroll
            for (int f = 0; f < 4; f++) {
                const float x = xs[f];
                int p = 0;
                #pragma unroll
                for (int s = 512; s >= 1; s >>= 1)
                    if (sB[f][p + s - 1] < x) p += s;
                const float2 ac = sAC[f][p];
                os[f] = fmaf(ac.x, x, ac.y);
            }
            *reinterpret_cast<float4*>(out + row * NCOL + g * 4) =
                make_float4(os[0], os[1], os[2], os[3]);
        }
    } else {
        __shared__ float scb[16 * 32];
        for (int i = tid; i < 16 * 32; i += TPB) scb[i] = cb[i];
        __syncthreads();

        const int cbase = (g - 12) * 4;   // cat feature 0..15 base
        #pragma unroll
        for (int e = 0; e < RPT; e++) {
            const int row = rbase + e * TPB;
            const float4 v = *reinterpret_cast<const float4*>(in + row * NCOL + g * 4);
            float4 o;
            o.x = scb[(cbase + 0) * 32 + (int)v.x];
            o.y = scb[(cbase + 1) * 32 + (int)v.y];
            o.z = scb[(cbase + 2) * 32 + (int)v.z];
            o.w = scb[(cbase + 3) * 32 + (int)v.w];
            *reinterpret_cast<float4*>(out + row * NCOL + g * 4) = o;
        }
    }
}

extern "C" void kernel_launch(void* const* d_in, const int* in_sizes, int n_in,
                              void* d_out, int out_size)
{
    const float* in = (const float*)d_in[0];
    const float* W0 = (const float*)d_in[1];
    const float* b0 = (const float*)d_in[2];
    const float* W1 = (const float*)d_in[3];
    const float* b1 = (const float*)d_in[4];
    const float* W2 = (const float*)d_in[5];
    const float* b2 = (const float*)d_in[6];
    const float* cb = (const float*)d_in[7];
    float* out = (float*)d_out;

    gam_precompute_kernel<<<NF, 256>>>(W0, b0, W1, b1, W2, b2);

    dim3 grid(BSZ / ROWS_BLK, 16, 1);   // 64 x 16
    gam_eval_kernel<<<grid, TPB>>>(in, cb, out);
}